// round 1
// baseline (speedup 1.0000x reference)
#include <cuda_runtime.h>
#include <cuda_fp16.h>
#include <stdint.h>

#define NB 8
#define BF 64
#define BN 2048

// Scratch (no allocations allowed in kernel_launch)
__device__ __half g_emb_h[NB * BF * BN];   // 2 MB
__device__ float  g_sqn[NB * BN];          // 64 KB
__device__ float  g_part_sum[256];
__device__ float  g_part_sq[256];
__device__ float  g_scale;

// ---------------- Pass 1: partial sum / sumsq over all emb elements ----------------
__global__ void reduce_kernel(const float* __restrict__ emb, int n) {
    float s = 0.f, s2 = 0.f;
    for (int i = blockIdx.x * blockDim.x + threadIdx.x; i < n; i += gridDim.x * blockDim.x) {
        float v = emb[i];
        s += v;
        s2 += v * v;
    }
    __shared__ float sh[256], sh2[256];
    int t = threadIdx.x;
    sh[t] = s; sh2[t] = s2;
    __syncthreads();
    for (int o = 128; o > 0; o >>= 1) {
        if (t < o) { sh[t] += sh[t + o]; sh2[t] += sh2[t + o]; }
        __syncthreads();
    }
    if (t == 0) { g_part_sum[blockIdx.x] = sh[0]; g_part_sq[blockIdx.x] = sh2[0]; }
}

// ---------------- Pass 2: finalize scale = 1/(var * F * SIGMA), ddof=1 ----------------
__global__ void finalize_kernel() {
    __shared__ float sh[256], sh2[256];
    int t = threadIdx.x;
    sh[t] = g_part_sum[t]; sh2[t] = g_part_sq[t];
    __syncthreads();
    for (int o = 128; o > 0; o >>= 1) {
        if (t < o) { sh[t] += sh[t + o]; sh2[t] += sh2[t + o]; }
        __syncthreads();
    }
    if (t == 0) {
        double n   = (double)(NB * BF * BN);
        double var = ((double)sh2[0] - (double)sh[0] * (double)sh[0] / n) / (n - 1.0);
        g_scale = (float)(1.0 / (var * (double)BF * 2.0));  // SIGMA = 2.0
    }
}

// ---------------- Pass 3: convert f32 -> f16 and compute per-(b,n) squared norms ----------------
__global__ void convert_kernel(const float* __restrict__ emb) {
    int b = blockIdx.y;
    int n = blockIdx.x * blockDim.x + threadIdx.x;
    const float* e = emb + (size_t)b * BF * BN;
    __half* h = g_emb_h + (size_t)b * BF * BN;
    float acc = 0.f;
#pragma unroll
    for (int f = 0; f < BF; ++f) {
        float v = e[f * BN + n];
        __half hv = __float2half(v);
        h[f * BN + n] = hv;
        float vf = __half2float(hv);
        acc += vf * vf;
    }
    g_sqn[b * BN + n] = acc;
}

// ---------------- Pass 4: 128x128-tile Gram GEMM (K=64) + exp epilogue ----------------
// out[b,i,j] = exp(scale * (2*gram - sqn_i - sqn_j))
__global__ __launch_bounds__(256, 2) void gemm_kernel(float* __restrict__ out) {
    // padded to 72 halves/row (144B): ldmatrix 8-row fetches are conflict-free
    __shared__ __half As[128][72];
    __shared__ __half Bs[128][72];

    int b  = blockIdx.z;
    int i0 = blockIdx.y * 128;
    int j0 = blockIdx.x * 128;
    const __half* E = g_emb_h + (size_t)b * BF * BN;
    int tid = threadIdx.x;

    // Load A/B tiles: [n_local][f] layout (coalesced gmem reads, 128 halves per f-row)
    for (int idx = tid; idx < BF * 128; idx += 256) {
        int f = idx >> 7;
        int n = idx & 127;
        As[n][f] = E[f * BN + i0 + n];
        Bs[n][f] = E[f * BN + j0 + n];
    }
    __syncthreads();

    int warp = tid >> 5, lane = tid & 31;
    int wm = (warp >> 2) * 64;   // warp rows: 0 or 64
    int wn = (warp & 3) * 32;    // warp cols: 0..96

    float c[4][4][4];
#pragma unroll
    for (int mt = 0; mt < 4; ++mt)
#pragma unroll
        for (int nt = 0; nt < 4; ++nt)
#pragma unroll
            for (int q = 0; q < 4; ++q) c[mt][nt][q] = 0.f;

#pragma unroll
    for (int kk = 0; kk < 4; ++kk) {
        int k0 = kk * 16;

        uint32_t a[4][4];
#pragma unroll
        for (int mt = 0; mt < 4; ++mt) {
            int row = wm + mt * 16 + (lane & 15);
            int col = k0 + ((lane >> 4) << 3);
            uint32_t addr = (uint32_t)__cvta_generic_to_shared(&As[row][col]);
            asm volatile("ldmatrix.sync.aligned.m8n8.x4.shared.b16 {%0,%1,%2,%3}, [%4];"
                         : "=r"(a[mt][0]), "=r"(a[mt][1]), "=r"(a[mt][2]), "=r"(a[mt][3])
                         : "r"(addr));
        }

        // B is n-major [n][k] in smem == col-major B operand: non-trans ldmatrix
        uint32_t bf[4][2];
#pragma unroll
        for (int nh = 0; nh < 2; ++nh) {
            int nrow = wn + nh * 16 + (lane & 7) + ((lane >> 4) << 3);
            int col  = k0 + (((lane >> 3) & 1) << 3);
            uint32_t addr = (uint32_t)__cvta_generic_to_shared(&Bs[nrow][col]);
            uint32_t r0, r1, r2, r3;
            asm volatile("ldmatrix.sync.aligned.m8n8.x4.shared.b16 {%0,%1,%2,%3}, [%4];"
                         : "=r"(r0), "=r"(r1), "=r"(r2), "=r"(r3)
                         : "r"(addr));
            bf[nh * 2][0] = r0; bf[nh * 2][1] = r1;
            bf[nh * 2 + 1][0] = r2; bf[nh * 2 + 1][1] = r3;
        }

#pragma unroll
        for (int mt = 0; mt < 4; ++mt)
#pragma unroll
            for (int nt = 0; nt < 4; ++nt) {
                asm volatile(
                    "mma.sync.aligned.m16n8k16.row.col.f32.f16.f16.f32 "
                    "{%0,%1,%2,%3}, {%4,%5,%6,%7}, {%8,%9}, {%0,%1,%2,%3};"
                    : "+f"(c[mt][nt][0]), "+f"(c[mt][nt][1]),
                      "+f"(c[mt][nt][2]), "+f"(c[mt][nt][3])
                    : "r"(a[mt][0]), "r"(a[mt][1]), "r"(a[mt][2]), "r"(a[mt][3]),
                      "r"(bf[nt][0]), "r"(bf[nt][1]));
            }
    }

    // Epilogue
    float s = g_scale;
    const float* SQ = g_sqn + b * BN;

    float sqi[4][2];
#pragma unroll
    for (int mt = 0; mt < 4; ++mt) {
        int r = wm + mt * 16 + (lane >> 2);
        sqi[mt][0] = __ldg(&SQ[i0 + r]);
        sqi[mt][1] = __ldg(&SQ[i0 + r + 8]);
    }
    float sqj[4][2];
#pragma unroll
    for (int nt = 0; nt < 4; ++nt) {
        int cc = wn + nt * 8 + 2 * (lane & 3);
        sqj[nt][0] = __ldg(&SQ[j0 + cc]);
        sqj[nt][1] = __ldg(&SQ[j0 + cc + 1]);
    }

#pragma unroll
    for (int mt = 0; mt < 4; ++mt) {
        int r = i0 + wm + mt * 16 + (lane >> 2);
#pragma unroll
        for (int nt = 0; nt < 4; ++nt) {
            int cc = j0 + wn + nt * 8 + 2 * (lane & 3);
            float2 v0, v1;
            v0.x = __expf(s * (2.f * c[mt][nt][0] - sqi[mt][0] - sqj[nt][0]));
            v0.y = __expf(s * (2.f * c[mt][nt][1] - sqi[mt][0] - sqj[nt][1]));
            v1.x = __expf(s * (2.f * c[mt][nt][2] - sqi[mt][1] - sqj[nt][0]));
            v1.y = __expf(s * (2.f * c[mt][nt][3] - sqi[mt][1] - sqj[nt][1]));
            float* o = out + ((size_t)b * BN + r) * BN + cc;
            *(float2*)o = v0;
            *(float2*)(o + (size_t)8 * BN) = v1;
        }
    }
}

extern "C" void kernel_launch(void* const* d_in, const int* in_sizes, int n_in,
                              void* d_out, int out_size) {
    (void)in_sizes; (void)n_in; (void)out_size;
    const float* emb = (const float*)d_in[1];  // d_in[0] = adj_in (unused by reference)
    float* out = (float*)d_out;

    reduce_kernel<<<256, 256>>>(emb, NB * BF * BN);
    finalize_kernel<<<1, 256>>>();
    dim3 gc(BN / 256, NB);
    convert_kernel<<<gc, 256>>>(emb);
    dim3 gg(16, 16, NB);
    gemm_kernel<<<gg, 256>>>(out);
}

// round 2
// speedup vs baseline: 1.5921x; 1.5921x over previous
#include <cuda_runtime.h>
#include <cuda_fp16.h>
#include <stdint.h>

#define NB 8
#define BF 64
#define BN 2048

// Scratch
__device__ __half g_emb_t[NB * BN * BF];   // transposed: [b][n][f], f contiguous (2 MB)
__device__ float  g_sqn[NB * BN];
__device__ float  g_part_sum[64];
__device__ float  g_part_sq[64];
__device__ float  g_scale;

// ---------------- Pass 1: convert f32->f16 transposed + sqn + std partial sums ----------------
__global__ void convert_reduce_kernel(const float* __restrict__ emb) {
    int b = blockIdx.y;
    int n = blockIdx.x * 256 + threadIdx.x;
    const float* e = emb + (size_t)b * BF * BN;

    float s = 0.f, s2 = 0.f, sq = 0.f;
    __half2 hv[32];
#pragma unroll
    for (int f = 0; f < BF; f += 2) {
        float v0 = e[f * BN + n];
        float v1 = e[(f + 1) * BN + n];
        s  += v0 + v1;
        s2 += v0 * v0 + v1 * v1;
        __half h0 = __float2half(v0), h1 = __float2half(v1);
        float w0 = __half2float(h0), w1 = __half2float(h1);
        sq += w0 * w0 + w1 * w1;
        hv[f >> 1] = __halves2half2(h0, h1);
    }
    g_sqn[b * BN + n] = sq;

    uint4* dst = (uint4*)(g_emb_t + ((size_t)b * BN + n) * BF);
    const uint4* src = (const uint4*)hv;
#pragma unroll
    for (int i = 0; i < 8; ++i) dst[i] = src[i];

    // block reduction of s, s2 (deterministic)
    __shared__ float sh[256], sh2[256];
    int t = threadIdx.x;
    sh[t] = s; sh2[t] = s2;
    __syncthreads();
    for (int o = 128; o > 0; o >>= 1) {
        if (t < o) { sh[t] += sh[t + o]; sh2[t] += sh2[t + o]; }
        __syncthreads();
    }
    if (t == 0) {
        int bi = blockIdx.y * 8 + blockIdx.x;
        g_part_sum[bi] = sh[0];
        g_part_sq[bi]  = sh2[0];
    }
}

// ---------------- Pass 2: finalize scale = 1/(var * F * SIGMA), ddof=1 ----------------
__global__ void finalize_kernel() {
    __shared__ float sh[64], sh2[64];
    int t = threadIdx.x;
    sh[t] = g_part_sum[t]; sh2[t] = g_part_sq[t];
    __syncthreads();
    for (int o = 32; o > 0; o >>= 1) {
        if (t < o) { sh[t] += sh[t + o]; sh2[t] += sh2[t + o]; }
        __syncthreads();
    }
    if (t == 0) {
        double nn  = (double)(NB * BF * BN);
        double var = ((double)sh2[0] - (double)sh[0] * (double)sh[0] / nn) / (nn - 1.0);
        g_scale = (float)(1.0 / (var * (double)BF * 2.0));  // SIGMA = 2.0
    }
}

// XOR swizzle for 128B rows: xor bits [4:6] with bits [7:9]
__device__ __forceinline__ uint32_t sw128(uint32_t off) {
    return off ^ (((off >> 7) & 7u) << 4);
}

// ---------------- Pass 3: 128x128-tile Gram GEMM (K=64) + exp epilogue ----------------
__global__ __launch_bounds__(256, 2) void gemm_kernel(float* __restrict__ out) {
    __shared__ __half As[128 * 64];   // 16 KB, swizzled 128B rows
    __shared__ __half Bs[128 * 64];

    int b  = blockIdx.z;
    int i0 = blockIdx.y * 128;
    int j0 = blockIdx.x * 128;
    const char* EA = (const char*)(g_emb_t + ((size_t)b * BN + i0) * BF);
    const char* EB = (const char*)(g_emb_t + ((size_t)b * BN + j0) * BF);
    int tid = threadIdx.x;

    uint32_t aBase = (uint32_t)__cvta_generic_to_shared(As);
    uint32_t bBase = (uint32_t)__cvta_generic_to_shared(Bs);

    // 1024 16B chunks per tile; 4 per thread, cp.async
#pragma unroll
    for (int t = 0; t < 4; ++t) {
        uint32_t off = (uint32_t)(tid + t * 256) * 16u;
        uint32_t sw  = sw128(off);
        asm volatile("cp.async.ca.shared.global [%0], [%1], 16;" :: "r"(aBase + sw), "l"(EA + off));
        asm volatile("cp.async.ca.shared.global [%0], [%1], 16;" :: "r"(bBase + sw), "l"(EB + off));
    }
    asm volatile("cp.async.commit_group;");
    asm volatile("cp.async.wait_group 0;");
    __syncthreads();

    int warp = tid >> 5, lane = tid & 31;
    int wm = (warp >> 2) * 64;   // warp rows: 0 or 64
    int wn = (warp & 3) * 32;    // warp cols: 0..96

    float c[4][4][4];
#pragma unroll
    for (int mt = 0; mt < 4; ++mt)
#pragma unroll
        for (int nt = 0; nt < 4; ++nt)
#pragma unroll
            for (int q = 0; q < 4; ++q) c[mt][nt][q] = 0.f;

#pragma unroll
    for (int kk = 0; kk < 4; ++kk) {
        int k0 = kk * 16;

        uint32_t a[4][4];
#pragma unroll
        for (int mt = 0; mt < 4; ++mt) {
            int row = wm + mt * 16 + (lane & 15);
            int col = k0 + ((lane >> 4) << 3);
            uint32_t addr = aBase + sw128((uint32_t)(row * 128 + col * 2));
            asm volatile("ldmatrix.sync.aligned.m8n8.x4.shared.b16 {%0,%1,%2,%3}, [%4];"
                         : "=r"(a[mt][0]), "=r"(a[mt][1]), "=r"(a[mt][2]), "=r"(a[mt][3])
                         : "r"(addr));
        }

        uint32_t bf[4][2];
#pragma unroll
        for (int nh = 0; nh < 2; ++nh) {
            int nrow = wn + nh * 16 + (lane & 7) + ((lane >> 4) << 3);
            int col  = k0 + (((lane >> 3) & 1) << 3);
            uint32_t addr = bBase + sw128((uint32_t)(nrow * 128 + col * 2));
            uint32_t r0, r1, r2, r3;
            asm volatile("ldmatrix.sync.aligned.m8n8.x4.shared.b16 {%0,%1,%2,%3}, [%4];"
                         : "=r"(r0), "=r"(r1), "=r"(r2), "=r"(r3)
                         : "r"(addr));
            bf[nh * 2][0] = r0;     bf[nh * 2][1] = r1;
            bf[nh * 2 + 1][0] = r2; bf[nh * 2 + 1][1] = r3;
        }

#pragma unroll
        for (int mt = 0; mt < 4; ++mt)
#pragma unroll
            for (int nt = 0; nt < 4; ++nt) {
                asm volatile(
                    "mma.sync.aligned.m16n8k16.row.col.f32.f16.f16.f32 "
                    "{%0,%1,%2,%3}, {%4,%5,%6,%7}, {%8,%9}, {%0,%1,%2,%3};"
                    : "+f"(c[mt][nt][0]), "+f"(c[mt][nt][1]),
                      "+f"(c[mt][nt][2]), "+f"(c[mt][nt][3])
                    : "r"(a[mt][0]), "r"(a[mt][1]), "r"(a[mt][2]), "r"(a[mt][3]),
                      "r"(bf[nt][0]), "r"(bf[nt][1]));
            }
    }

    // Epilogue: out = exp(scale * (2*gram - sqn_i - sqn_j))
    float s = g_scale;
    const float* SQ = g_sqn + b * BN;

    float sqi[4][2];
#pragma unroll
    for (int mt = 0; mt < 4; ++mt) {
        int r = wm + mt * 16 + (lane >> 2);
        sqi[mt][0] = __ldg(&SQ[i0 + r]);
        sqi[mt][1] = __ldg(&SQ[i0 + r + 8]);
    }
    float sqj[4][2];
#pragma unroll
    for (int nt = 0; nt < 4; ++nt) {
        int cc = wn + nt * 8 + 2 * (lane & 3);
        sqj[nt][0] = __ldg(&SQ[j0 + cc]);
        sqj[nt][1] = __ldg(&SQ[j0 + cc + 1]);
    }

#pragma unroll
    for (int mt = 0; mt < 4; ++mt) {
        int r = i0 + wm + mt * 16 + (lane >> 2);
#pragma unroll
        for (int nt = 0; nt < 4; ++nt) {
            int cc = j0 + wn + nt * 8 + 2 * (lane & 3);
            float2 v0, v1;
            v0.x = __expf(s * (2.f * c[mt][nt][0] - sqi[mt][0] - sqj[nt][0]));
            v0.y = __expf(s * (2.f * c[mt][nt][1] - sqi[mt][0] - sqj[nt][1]));
            v1.x = __expf(s * (2.f * c[mt][nt][2] - sqi[mt][1] - sqj[nt][0]));
            v1.y = __expf(s * (2.f * c[mt][nt][3] - sqi[mt][1] - sqj[nt][1]));
            float* o = out + ((size_t)b * BN + r) * BN + cc;
            *(float2*)o = v0;
            *(float2*)(o + (size_t)8 * BN) = v1;
        }
    }
}

extern "C" void kernel_launch(void* const* d_in, const int* in_sizes, int n_in,
                              void* d_out, int out_size) {
    (void)in_sizes; (void)n_in; (void)out_size;
    const float* emb = (const float*)d_in[1];  // d_in[0] = adj_in (unused by reference)
    float* out = (float*)d_out;

    dim3 gc(BN / 256, NB);
    convert_reduce_kernel<<<gc, 256>>>(emb);
    finalize_kernel<<<1, 64>>>();
    dim3 gg(16, 16, NB);
    gemm_kernel<<<gg, 256>>>(out);
}

// round 3
// speedup vs baseline: 1.6015x; 1.0059x over previous
#include <cuda_runtime.h>
#include <cuda_fp16.h>
#include <stdint.h>

#define NB 8
#define BF 64
#define BN 2048

// Scratch
__device__ __half g_emb_t[NB * BN * BF];   // transposed: [b][n][f], f contiguous (2 MB)
__device__ float  g_sqn[NB * BN];
__device__ float  g_part_sum[256];
__device__ float  g_part_sq[256];

// ---------------- Pass 1: convert f32->f16 transposed + sqn + std partial sums ----------------
// 4 threads per column n, 16 f each. grid (32, 8) x 256 threads.
__global__ void convert_reduce_kernel(const float* __restrict__ emb) {
    int b   = blockIdx.y;
    int tid = threadIdx.x;
    int fq  = tid & 3;        // f quarter
    int nl  = tid >> 2;       // 0..63
    int n   = blockIdx.x * 64 + nl;

    const float* e = emb + (size_t)b * BF * BN + (size_t)(fq * 16) * BN + n;

    float s = 0.f, s2 = 0.f, sq = 0.f;
    __half2 hv[8];
#pragma unroll
    for (int i = 0; i < 16; i += 2) {
        float v0 = e[(size_t)i * BN];
        float v1 = e[(size_t)(i + 1) * BN];
        s  += v0 + v1;
        s2 += v0 * v0 + v1 * v1;
        __half h0 = __float2half(v0), h1 = __float2half(v1);
        float w0 = __half2float(h0), w1 = __half2float(h1);
        sq += w0 * w0 + w1 * w1;
        hv[i >> 1] = __halves2half2(h0, h1);
    }
    // combine sq across the 4 fq lanes (adjacent lanes)
    sq += __shfl_xor_sync(0xffffffffu, sq, 1);
    sq += __shfl_xor_sync(0xffffffffu, sq, 2);
    if (fq == 0) g_sqn[b * BN + n] = sq;

    uint4* dst = (uint4*)(g_emb_t + ((size_t)b * BN + n) * BF + fq * 16);
    const uint4* src = (const uint4*)hv;
    dst[0] = src[0];
    dst[1] = src[1];

    // deterministic block reduction of s, s2
    __shared__ float sh[256], sh2[256];
    sh[tid] = s; sh2[tid] = s2;
    __syncthreads();
    for (int o = 128; o > 0; o >>= 1) {
        if (tid < o) { sh[tid] += sh[tid + o]; sh2[tid] += sh2[tid + o]; }
        __syncthreads();
    }
    if (tid == 0) {
        int bi = b * 32 + blockIdx.x;
        g_part_sum[bi] = sh[0];
        g_part_sq[bi]  = sh2[0];
    }
}

// XOR swizzle for 128B rows: xor bits [4:6] with bits [7:9]
__device__ __forceinline__ uint32_t sw128(uint32_t off) {
    return off ^ (((off >> 7) & 7u) << 4);
}

// ---------------- Pass 2: 128x128-tile Gram GEMM (K=64) + exp epilogue ----------------
__global__ __launch_bounds__(256, 2) void gemm_kernel(float* __restrict__ out) {
    __shared__ __half As[128 * 64];   // 16 KB, swizzled 128B rows
    __shared__ __half Bs[128 * 64];
    __shared__ float  sSqI[128];
    __shared__ float  sSqJ[128];
    __shared__ float  s_scale;

    int b  = blockIdx.z;
    int i0 = blockIdx.y * 128;
    int j0 = blockIdx.x * 128;
    const char* EA = (const char*)(g_emb_t + ((size_t)b * BN + i0) * BF);
    const char* EB = (const char*)(g_emb_t + ((size_t)b * BN + j0) * BF);
    int tid = threadIdx.x;

    uint32_t aBase = (uint32_t)__cvta_generic_to_shared(As);
    uint32_t bBase = (uint32_t)__cvta_generic_to_shared(Bs);

    // tile loads: 1024 16B chunks per tile, 4 per thread
#pragma unroll
    for (int t = 0; t < 4; ++t) {
        uint32_t off = (uint32_t)(tid + t * 256) * 16u;
        uint32_t sw  = sw128(off);
        asm volatile("cp.async.ca.shared.global [%0], [%1], 16;" :: "r"(aBase + sw), "l"(EA + off));
        asm volatile("cp.async.ca.shared.global [%0], [%1], 16;" :: "r"(bBase + sw), "l"(EB + off));
    }
    // sqn slices into smem (32 x 16B)
    if (tid < 32) {
        uint32_t sI = (uint32_t)__cvta_generic_to_shared(sSqI) + tid * 16u;
        uint32_t sJ = (uint32_t)__cvta_generic_to_shared(sSqJ) + tid * 16u;
        const char* gI = (const char*)(g_sqn + b * BN + i0) + tid * 16;
        const char* gJ = (const char*)(g_sqn + b * BN + j0) + tid * 16;
        asm volatile("cp.async.ca.shared.global [%0], [%1], 16;" :: "r"(sI), "l"(gI));
        asm volatile("cp.async.ca.shared.global [%0], [%1], 16;" :: "r"(sJ), "l"(gJ));
    }
    asm volatile("cp.async.commit_group;");

    // scale reduction (redundant per block; overlapped with cp.async)
    if (tid < 32) {
        float ps = 0.f, pq = 0.f;
#pragma unroll
        for (int i = 0; i < 8; ++i) {
            ps += g_part_sum[tid + 32 * i];
            pq += g_part_sq[tid + 32 * i];
        }
#pragma unroll
        for (int o = 16; o > 0; o >>= 1) {
            ps += __shfl_xor_sync(0xffffffffu, ps, o);
            pq += __shfl_xor_sync(0xffffffffu, pq, o);
        }
        if (tid == 0) {
            double nn  = (double)(NB * BF * BN);
            double var = ((double)pq - (double)ps * (double)ps / nn) / (nn - 1.0);
            s_scale = (float)(1.0 / (var * (double)BF * 2.0));  // SIGMA = 2.0
        }
    }

    asm volatile("cp.async.wait_group 0;");
    __syncthreads();

    int warp = tid >> 5, lane = tid & 31;
    int wm = (warp >> 2) * 64;   // warp rows: 0 or 64
    int wn = (warp & 3) * 32;    // warp cols: 0..96

    float c[4][4][4];
#pragma unroll
    for (int mt = 0; mt < 4; ++mt)
#pragma unroll
        for (int nt = 0; nt < 4; ++nt)
#pragma unroll
            for (int q = 0; q < 4; ++q) c[mt][nt][q] = 0.f;

#pragma unroll
    for (int kk = 0; kk < 4; ++kk) {
        int k0 = kk * 16;

        uint32_t a[4][4];
#pragma unroll
        for (int mt = 0; mt < 4; ++mt) {
            int row = wm + mt * 16 + (lane & 15);
            int col = k0 + ((lane >> 4) << 3);
            uint32_t addr = aBase + sw128((uint32_t)(row * 128 + col * 2));
            asm volatile("ldmatrix.sync.aligned.m8n8.x4.shared.b16 {%0,%1,%2,%3}, [%4];"
                         : "=r"(a[mt][0]), "=r"(a[mt][1]), "=r"(a[mt][2]), "=r"(a[mt][3])
                         : "r"(addr));
        }

        uint32_t bf[4][2];
#pragma unroll
        for (int nh = 0; nh < 2; ++nh) {
            int nrow = wn + nh * 16 + (lane & 7) + ((lane >> 4) << 3);
            int col  = k0 + (((lane >> 3) & 1) << 3);
            uint32_t addr = bBase + sw128((uint32_t)(nrow * 128 + col * 2));
            uint32_t r0, r1, r2, r3;
            asm volatile("ldmatrix.sync.aligned.m8n8.x4.shared.b16 {%0,%1,%2,%3}, [%4];"
                         : "=r"(r0), "=r"(r1), "=r"(r2), "=r"(r3)
                         : "r"(addr));
            bf[nh * 2][0] = r0;     bf[nh * 2][1] = r1;
            bf[nh * 2 + 1][0] = r2; bf[nh * 2 + 1][1] = r3;
        }

#pragma unroll
        for (int mt = 0; mt < 4; ++mt)
#pragma unroll
            for (int nt = 0; nt < 4; ++nt) {
                asm volatile(
                    "mma.sync.aligned.m16n8k16.row.col.f32.f16.f16.f32 "
                    "{%0,%1,%2,%3}, {%4,%5,%6,%7}, {%8,%9}, {%0,%1,%2,%3};"
                    : "+f"(c[mt][nt][0]), "+f"(c[mt][nt][1]),
                      "+f"(c[mt][nt][2]), "+f"(c[mt][nt][3])
                    : "r"(a[mt][0]), "r"(a[mt][1]), "r"(a[mt][2]), "r"(a[mt][3]),
                      "r"(bf[nt][0]), "r"(bf[nt][1]));
            }
    }

    // Epilogue: out = exp(scale * (2*gram - sqn_i - sqn_j))
    float s = s_scale;

    float sqi[4][2];
#pragma unroll
    for (int mt = 0; mt < 4; ++mt) {
        int r = wm + mt * 16 + (lane >> 2);
        sqi[mt][0] = sSqI[r];
        sqi[mt][1] = sSqI[r + 8];
    }
    float sqj[4][2];
#pragma unroll
    for (int nt = 0; nt < 4; ++nt) {
        int cc = wn + nt * 8 + 2 * (lane & 3);
        sqj[nt][0] = sSqJ[cc];
        sqj[nt][1] = sSqJ[cc + 1];
    }

#pragma unroll
    for (int mt = 0; mt < 4; ++mt) {
        int r = i0 + wm + mt * 16 + (lane >> 2);
#pragma unroll
        for (int nt = 0; nt < 4; ++nt) {
            int cc = j0 + wn + nt * 8 + 2 * (lane & 3);
            float2 v0, v1;
            v0.x = __expf(s * (2.f * c[mt][nt][0] - sqi[mt][0] - sqj[nt][0]));
            v0.y = __expf(s * (2.f * c[mt][nt][1] - sqi[mt][0] - sqj[nt][1]));
            v1.x = __expf(s * (2.f * c[mt][nt][2] - sqi[mt][1] - sqj[nt][0]));
            v1.y = __expf(s * (2.f * c[mt][nt][3] - sqi[mt][1] - sqj[nt][1]));
            float* o = out + ((size_t)b * BN + r) * BN + cc;
            __stcs((float2*)o, v0);
            __stcs((float2*)(o + (size_t)8 * BN), v1);
        }
    }
}

extern "C" void kernel_launch(void* const* d_in, const int* in_sizes, int n_in,
                              void* d_out, int out_size) {
    (void)in_sizes; (void)n_in; (void)out_size;
    const float* emb = (const float*)d_in[1];  // d_in[0] = adj_in (unused by reference)
    float* out = (float*)d_out;

    dim3 gc(BN / 64, NB);
    convert_reduce_kernel<<<gc, 256>>>(emb);
    dim3 gg(16, 16, NB);
    gemm_kernel<<<gg, 256>>>(out);
}

// round 4
// speedup vs baseline: 1.7693x; 1.1048x over previous
#include <cuda_runtime.h>
#include <cuda_fp16.h>
#include <stdint.h>

#define NB 8
#define BF 64
#define BN 2048

// Scratch
__device__ __half g_emb_t[NB * BN * BF];   // transposed: [b][n][f], f contiguous (2 MB)
__device__ float  g_sqn[NB * BN];
__device__ float  g_part_sum[256];
__device__ float  g_part_sq[256];

// ---------------- Pass 1: convert f32->f16 transposed + sqn + std partial sums ----------------
__global__ void convert_reduce_kernel(const float* __restrict__ emb) {
    int b   = blockIdx.y;
    int tid = threadIdx.x;
    int fq  = tid & 3;
    int nl  = tid >> 2;
    int n   = blockIdx.x * 64 + nl;

    const float* e = emb + (size_t)b * BF * BN + (size_t)(fq * 16) * BN + n;

    float s = 0.f, s2 = 0.f, sq = 0.f;
    __half2 hv[8];
#pragma unroll
    for (int i = 0; i < 16; i += 2) {
        float v0 = e[(size_t)i * BN];
        float v1 = e[(size_t)(i + 1) * BN];
        s  += v0 + v1;
        s2 += v0 * v0 + v1 * v1;
        __half h0 = __float2half(v0), h1 = __float2half(v1);
        float w0 = __half2float(h0), w1 = __half2float(h1);
        sq += w0 * w0 + w1 * w1;
        hv[i >> 1] = __halves2half2(h0, h1);
    }
    sq += __shfl_xor_sync(0xffffffffu, sq, 1);
    sq += __shfl_xor_sync(0xffffffffu, sq, 2);
    if (fq == 0) g_sqn[b * BN + n] = sq;

    uint4* dst = (uint4*)(g_emb_t + ((size_t)b * BN + n) * BF + fq * 16);
    const uint4* src = (const uint4*)hv;
    dst[0] = src[0];
    dst[1] = src[1];

    __shared__ float sh[256], sh2[256];
    sh[tid] = s; sh2[tid] = s2;
    __syncthreads();
    for (int o = 128; o > 0; o >>= 1) {
        if (tid < o) { sh[tid] += sh[tid + o]; sh2[tid] += sh2[tid + o]; }
        __syncthreads();
    }
    if (tid == 0) {
        int bi = b * 32 + blockIdx.x;
        g_part_sum[bi] = sh[0];
        g_part_sq[bi]  = sh2[0];
    }
}

// XOR swizzle for 128B rows: xor bits [4:6] with bits [7:9]
__device__ __forceinline__ uint32_t sw128(uint32_t off) {
    return off ^ (((off >> 7) & 7u) << 4);
}

// ---------------- Pass 2: upper-triangle Gram GEMM (K=64) + exp + mirrored store ----------------
__global__ __launch_bounds__(256, 2) void gemm_kernel(float* __restrict__ out) {
    // 32 KB buffer: A/B half tiles during MMA; float[64][128] transpose staging in epilogue
    __shared__ __align__(16) char sBuf[32768];
    __shared__ float sSqI[128];
    __shared__ float sSqJ[128];
    __shared__ float s_l2scale;

    __half* As = (__half*)sBuf;
    __half* Bs = (__half*)(sBuf + 16384);
    float*  stg = (float*)sBuf;

    int b = blockIdx.z;
    // map linear t -> upper-triangle tile pair (ti <= tj), 16x16 tiles, 136 pairs
    int t = blockIdx.x;
    int ti = (int)(16.5f - sqrtf(272.25f - 2.0f * (float)t));
    if (ti > 0 && 16 * ti - (ti * (ti - 1)) / 2 > t) --ti;
    while (16 * (ti + 1) - ((ti + 1) * ti) / 2 <= t) ++ti;
    int tj = ti + (t - (16 * ti - (ti * (ti - 1)) / 2));

    int i0 = ti * 128;
    int j0 = tj * 128;
    const char* EA = (const char*)(g_emb_t + ((size_t)b * BN + i0) * BF);
    const char* EB = (const char*)(g_emb_t + ((size_t)b * BN + j0) * BF);
    int tid = threadIdx.x;

    uint32_t aBase = (uint32_t)__cvta_generic_to_shared(As);
    uint32_t bBase = (uint32_t)__cvta_generic_to_shared(Bs);

#pragma unroll
    for (int tt = 0; tt < 4; ++tt) {
        uint32_t off = (uint32_t)(tid + tt * 256) * 16u;
        uint32_t sw  = sw128(off);
        asm volatile("cp.async.ca.shared.global [%0], [%1], 16;" :: "r"(aBase + sw), "l"(EA + off));
        asm volatile("cp.async.ca.shared.global [%0], [%1], 16;" :: "r"(bBase + sw), "l"(EB + off));
    }
    if (tid < 32) {
        uint32_t sI = (uint32_t)__cvta_generic_to_shared(sSqI) + tid * 16u;
        uint32_t sJ = (uint32_t)__cvta_generic_to_shared(sSqJ) + tid * 16u;
        const char* gI = (const char*)(g_sqn + b * BN + i0) + tid * 16;
        const char* gJ = (const char*)(g_sqn + b * BN + j0) + tid * 16;
        asm volatile("cp.async.ca.shared.global [%0], [%1], 16;" :: "r"(sI), "l"(gI));
        asm volatile("cp.async.ca.shared.global [%0], [%1], 16;" :: "r"(sJ), "l"(gJ));
    }
    asm volatile("cp.async.commit_group;");

    // scale reduction (redundant per block; overlapped with cp.async). stores log2(e)/(var*F*SIGMA)
    if (tid < 32) {
        float ps = 0.f, pq = 0.f;
#pragma unroll
        for (int i = 0; i < 8; ++i) {
            ps += g_part_sum[tid + 32 * i];
            pq += g_part_sq[tid + 32 * i];
        }
#pragma unroll
        for (int o = 16; o > 0; o >>= 1) {
            ps += __shfl_xor_sync(0xffffffffu, ps, o);
            pq += __shfl_xor_sync(0xffffffffu, pq, o);
        }
        if (tid == 0) {
            double nn  = (double)(NB * BF * BN);
            double var = ((double)pq - (double)ps * (double)ps / nn) / (nn - 1.0);
            s_l2scale = (float)(1.4426950408889634 / (var * (double)BF * 2.0));
        }
    }

    asm volatile("cp.async.wait_group 0;");
    __syncthreads();

    int warp = tid >> 5, lane = tid & 31;
    int wm = (warp >> 2) * 64;
    int wn = (warp & 3) * 32;

    float c[4][4][4];
#pragma unroll
    for (int mt = 0; mt < 4; ++mt)
#pragma unroll
        for (int nt = 0; nt < 4; ++nt)
#pragma unroll
            for (int q = 0; q < 4; ++q) c[mt][nt][q] = 0.f;

#pragma unroll
    for (int kk = 0; kk < 4; ++kk) {
        int k0 = kk * 16;

        uint32_t a[4][4];
#pragma unroll
        for (int mt = 0; mt < 4; ++mt) {
            int row = wm + mt * 16 + (lane & 15);
            int col = k0 + ((lane >> 4) << 3);
            uint32_t addr = aBase + sw128((uint32_t)(row * 128 + col * 2));
            asm volatile("ldmatrix.sync.aligned.m8n8.x4.shared.b16 {%0,%1,%2,%3}, [%4];"
                         : "=r"(a[mt][0]), "=r"(a[mt][1]), "=r"(a[mt][2]), "=r"(a[mt][3])
                         : "r"(addr));
        }

        uint32_t bf[4][2];
#pragma unroll
        for (int nh = 0; nh < 2; ++nh) {
            int nrow = wn + nh * 16 + (lane & 7) + ((lane >> 4) << 3);
            int col  = k0 + (((lane >> 3) & 1) << 3);
            uint32_t addr = bBase + sw128((uint32_t)(nrow * 128 + col * 2));
            uint32_t r0, r1, r2, r3;
            asm volatile("ldmatrix.sync.aligned.m8n8.x4.shared.b16 {%0,%1,%2,%3}, [%4];"
                         : "=r"(r0), "=r"(r1), "=r"(r2), "=r"(r3)
                         : "r"(addr));
            bf[nh * 2][0] = r0;     bf[nh * 2][1] = r1;
            bf[nh * 2 + 1][0] = r2; bf[nh * 2 + 1][1] = r3;
        }

#pragma unroll
        for (int mt = 0; mt < 4; ++mt)
#pragma unroll
            for (int nt = 0; nt < 4; ++nt) {
                asm volatile(
                    "mma.sync.aligned.m16n8k16.row.col.f32.f16.f16.f32 "
                    "{%0,%1,%2,%3}, {%4,%5,%6,%7}, {%8,%9}, {%0,%1,%2,%3};"
                    : "+f"(c[mt][nt][0]), "+f"(c[mt][nt][1]),
                      "+f"(c[mt][nt][2]), "+f"(c[mt][nt][3])
                    : "r"(a[mt][0]), "r"(a[mt][1]), "r"(a[mt][2]), "r"(a[mt][3]),
                      "r"(bf[nt][0]), "r"(bf[nt][1]));
            }
    }

    // ---- Epilogue: v = exp2(k2*gram - l2s*qi - l2s*qj) ----
    float l2s = s_l2scale;
    float k2  = 2.f * l2s;

    float sqi[4][2];
#pragma unroll
    for (int mt = 0; mt < 4; ++mt) {
        int r = wm + mt * 16 + (lane >> 2);
        sqi[mt][0] = -l2s * sSqI[r];
        sqi[mt][1] = -l2s * sSqI[r + 8];
    }
    float sqj[4][2];
#pragma unroll
    for (int nt = 0; nt < 4; ++nt) {
        int cc = wn + nt * 8 + 2 * (lane & 3);
        sqj[nt][0] = -l2s * sSqJ[cc];
        sqj[nt][1] = -l2s * sSqJ[cc + 1];
    }

#pragma unroll
    for (int mt = 0; mt < 4; ++mt)
#pragma unroll
        for (int nt = 0; nt < 4; ++nt) {
            c[mt][nt][0] = exp2f(fmaf(k2, c[mt][nt][0], sqi[mt][0]) + sqj[nt][0]);
            c[mt][nt][1] = exp2f(fmaf(k2, c[mt][nt][1], sqi[mt][0]) + sqj[nt][1]);
            c[mt][nt][2] = exp2f(fmaf(k2, c[mt][nt][2], sqi[mt][1]) + sqj[nt][0]);
            c[mt][nt][3] = exp2f(fmaf(k2, c[mt][nt][3], sqi[mt][1]) + sqj[nt][1]);
        }

    // direct store of (i,j) tile
#pragma unroll
    for (int mt = 0; mt < 4; ++mt) {
        int r = i0 + wm + mt * 16 + (lane >> 2);
#pragma unroll
        for (int nt = 0; nt < 4; ++nt) {
            int cc = j0 + wn + nt * 8 + 2 * (lane & 3);
            float2 v0, v1;
            v0.x = c[mt][nt][0]; v0.y = c[mt][nt][1];
            v1.x = c[mt][nt][2]; v1.y = c[mt][nt][3];
            float* o = out + ((size_t)b * BN + r) * BN + cc;
            __stcs((float2*)o, v0);
            __stcs((float2*)(o + (size_t)8 * BN), v1);
        }
    }

    if (i0 == j0) return;

    // mirrored store of (j,i) tile via smem transpose, two 64-column passes
#pragma unroll
    for (int h = 0; h < 2; ++h) {
        __syncthreads();   // smem free (MMA done / previous pass consumed)
#pragma unroll
        for (int mt = 0; mt < 4; ++mt)
#pragma unroll
            for (int nt2 = 0; nt2 < 2; ++nt2) {
                int nt = 2 * h + nt2;
#pragma unroll
                for (int q = 0; q < 4; ++q) {
                    int r  = wm + mt * 16 + (lane >> 2) + 8 * (q >> 1);
                    int cc = wn + nt * 8 + 2 * (lane & 3) + (q & 1);
                    int srow  = ((cc >> 5) << 4) | (cc & 15);
                    int chunk = (r >> 2) ^ (cc & 7);      // conflict-free swizzle
                    stg[srow * 128 + chunk * 4 + (r & 3)] = c[mt][nt][q];
                }
            }
        __syncthreads();
#pragma unroll
        for (int it = 0; it < 8; ++it) {
            int idx   = tid + it * 256;      // 0..2047
            int srow  = idx >> 5;
            int chunk = idx & 31;
            int cc = ((srow >> 4) << 5) + 16 * h + (srow & 15);
            int rchunk = chunk ^ (srow & 7);
            float4 v4 = *(float4*)&stg[srow * 128 + rchunk * 4];
            __stcs((float4*)(out + ((size_t)b * BN + j0 + cc) * BN + i0 + chunk * 4), v4);
        }
    }
}

extern "C" void kernel_launch(void* const* d_in, const int* in_sizes, int n_in,
                              void* d_out, int out_size) {
    (void)in_sizes; (void)n_in; (void)out_size;
    const float* emb = (const float*)d_in[1];  // d_in[0] = adj_in (unused by reference)
    float* out = (float*)d_out;

    dim3 gc(BN / 64, NB);
    convert_reduce_kernel<<<gc, 256>>>(emb);
    dim3 gg(136, 1, NB);
    gemm_kernel<<<gg, 256>>>(out);
}

// round 5
// speedup vs baseline: 1.8411x; 1.0406x over previous
#include <cuda_runtime.h>
#include <cuda_fp16.h>
#include <stdint.h>

#define NB 8
#define BF 64
#define BN 2048
#define GRID_P 296            // persistent CTAs (148 SMs x 2)
#define NPAIR 136             // upper-triangle 16x16 tile pairs
#define NTASK (NPAIR * NB)    // 1088

// Scratch
__device__ __half g_emb_t[NB * BN * BF];   // transposed: [b][n][f], f contiguous (2 MB)
__device__ float  g_sqn[NB * BN];
__device__ float  g_part_sum[256];
__device__ float  g_part_sq[256];

// ---------------- Pass 1: convert f32->f16 transposed + sqn + std partial sums ----------------
__global__ void convert_reduce_kernel(const float* __restrict__ emb) {
    int b   = blockIdx.y;
    int tid = threadIdx.x;
    int fq  = tid & 3;
    int nl  = tid >> 2;
    int n   = blockIdx.x * 64 + nl;

    const float* e = emb + (size_t)b * BF * BN + (size_t)(fq * 16) * BN + n;

    float s = 0.f, s2 = 0.f, sq = 0.f;
    __half2 hv[8];
#pragma unroll
    for (int i = 0; i < 16; i += 2) {
        float v0 = e[(size_t)i * BN];
        float v1 = e[(size_t)(i + 1) * BN];
        s  += v0 + v1;
        s2 += v0 * v0 + v1 * v1;
        __half h0 = __float2half(v0), h1 = __float2half(v1);
        float w0 = __half2float(h0), w1 = __half2float(h1);
        sq += w0 * w0 + w1 * w1;
        hv[i >> 1] = __halves2half2(h0, h1);
    }
    sq += __shfl_xor_sync(0xffffffffu, sq, 1);
    sq += __shfl_xor_sync(0xffffffffu, sq, 2);
    if (fq == 0) g_sqn[b * BN + n] = sq;

    uint4* dst = (uint4*)(g_emb_t + ((size_t)b * BN + n) * BF + fq * 16);
    const uint4* src = (const uint4*)hv;
    dst[0] = src[0];
    dst[1] = src[1];

    __shared__ float sh[256], sh2[256];
    sh[tid] = s; sh2[tid] = s2;
    __syncthreads();
    for (int o = 128; o > 0; o >>= 1) {
        if (tid < o) { sh[tid] += sh[tid + o]; sh2[tid] += sh2[tid + o]; }
        __syncthreads();
    }
    if (tid == 0) {
        int bi = b * 32 + blockIdx.x;
        g_part_sum[bi] = sh[0];
        g_part_sq[bi]  = sh2[0];
    }
}

// XOR swizzle for 128B rows
__device__ __forceinline__ uint32_t sw128(uint32_t off) {
    return off ^ (((off >> 7) & 7u) << 4);
}

__device__ __forceinline__ void decode_task(int task, int& b, int& i0, int& j0) {
    b = task / NPAIR;
    int t = task - b * NPAIR;
    int ti = (int)(16.5f - sqrtf(272.25f - 2.0f * (float)t));
    if (ti > 0 && 16 * ti - (ti * (ti - 1)) / 2 > t) --ti;
    while (16 * (ti + 1) - ((ti + 1) * ti) / 2 <= t) ++ti;
    int tj = ti + (t - (16 * ti - (ti * (ti - 1)) / 2));
    i0 = ti * 128;
    j0 = tj * 128;
}

// issue cp.async loads for one task into buffer `buf`
__device__ __forceinline__ void issue_load(int b, int i0, int j0,
                                           uint32_t abBase, uint32_t sqBase, int tid) {
    const char* EA = (const char*)(g_emb_t + ((size_t)b * BN + i0) * BF);
    const char* EB = (const char*)(g_emb_t + ((size_t)b * BN + j0) * BF);
#pragma unroll
    for (int tt = 0; tt < 4; ++tt) {
        uint32_t off = (uint32_t)(tid + tt * 256) * 16u;
        uint32_t sw  = sw128(off);
        asm volatile("cp.async.ca.shared.global [%0], [%1], 16;" :: "r"(abBase + sw),          "l"(EA + off));
        asm volatile("cp.async.ca.shared.global [%0], [%1], 16;" :: "r"(abBase + 16384u + sw), "l"(EB + off));
    }
    if (tid < 32) {
        const char* gI = (const char*)(g_sqn + b * BN + i0) + tid * 16;
        const char* gJ = (const char*)(g_sqn + b * BN + j0) + tid * 16;
        asm volatile("cp.async.ca.shared.global [%0], [%1], 16;" :: "r"(sqBase + tid * 16u),        "l"(gI));
        asm volatile("cp.async.ca.shared.global [%0], [%1], 16;" :: "r"(sqBase + 512u + tid * 16u), "l"(gJ));
    }
}

// ---------------- Pass 2: persistent upper-triangle Gram GEMM + exp + mirrored store ----------------
// dynamic smem layout: [0,32K) buf0 A|B, [32K,64K) buf1 A|B, [64K,+2K) sq[2][I|J][128], [+2K,+4) scale
__global__ __launch_bounds__(256, 2) void gemm_kernel(float* __restrict__ out) {
    extern __shared__ __align__(16) char smem[];
    float* sSq     = (float*)(smem + 65536);
    float* s_scale = (float*)(smem + 65536 + 2048);

    int tid = threadIdx.x;
    uint32_t smemBase = (uint32_t)__cvta_generic_to_shared(smem);
    uint32_t sqBaseU  = smemBase + 65536u;

    int task = blockIdx.x;
    int b, i0, j0;
    decode_task(task, b, i0, j0);
    issue_load(b, i0, j0, smemBase, sqBaseU, tid);
    asm volatile("cp.async.commit_group;");

    // scale reduction, once per CTA (overlapped with first load)
    if (tid < 32) {
        float ps = 0.f, pq = 0.f;
#pragma unroll
        for (int i = 0; i < 8; ++i) {
            ps += g_part_sum[tid + 32 * i];
            pq += g_part_sq[tid + 32 * i];
        }
#pragma unroll
        for (int o = 16; o > 0; o >>= 1) {
            ps += __shfl_xor_sync(0xffffffffu, ps, o);
            pq += __shfl_xor_sync(0xffffffffu, pq, o);
        }
        if (tid == 0) {
            double nn  = (double)(NB * BF * BN);
            double var = ((double)pq - (double)ps * (double)ps / nn) / (nn - 1.0);
            *s_scale = (float)(1.4426950408889634 / (var * (double)BF * 2.0));
        }
    }

    asm volatile("cp.async.wait_group 0;");
    __syncthreads();

    int warp = tid >> 5, lane = tid & 31;
    int wm = (warp >> 2) * 64;
    int wn = (warp & 3) * 32;
    float l2s = *s_scale;
    float k2  = 2.f * l2s;

    int it = 0;
    while (true) {
        int buf = it & 1;
        uint32_t aBase = smemBase + (uint32_t)buf * 32768u;
        uint32_t bBase = aBase + 16384u;

        // prefetch next task into other buffer
        int ntask = task + GRID_P;
        bool have_next = ntask < NTASK;
        int nb, ni, nj;
        if (have_next) {
            decode_task(ntask, nb, ni, nj);
            issue_load(nb, ni, nj, smemBase + (uint32_t)(buf ^ 1) * 32768u,
                       sqBaseU + (uint32_t)(buf ^ 1) * 1024u, tid);
        }
        asm volatile("cp.async.commit_group;");

        // ---- MMA ----
        float c[4][4][4];
#pragma unroll
        for (int mt = 0; mt < 4; ++mt)
#pragma unroll
            for (int nt = 0; nt < 4; ++nt)
#pragma unroll
                for (int q = 0; q < 4; ++q) c[mt][nt][q] = 0.f;

#pragma unroll
        for (int kk = 0; kk < 4; ++kk) {
            int k0 = kk * 16;

            uint32_t a[4][4];
#pragma unroll
            for (int mt = 0; mt < 4; ++mt) {
                int row = wm + mt * 16 + (lane & 15);
                int col = k0 + ((lane >> 4) << 3);
                uint32_t addr = aBase + sw128((uint32_t)(row * 128 + col * 2));
                asm volatile("ldmatrix.sync.aligned.m8n8.x4.shared.b16 {%0,%1,%2,%3}, [%4];"
                             : "=r"(a[mt][0]), "=r"(a[mt][1]), "=r"(a[mt][2]), "=r"(a[mt][3])
                             : "r"(addr));
            }

            uint32_t bfr[4][2];
#pragma unroll
            for (int nh = 0; nh < 2; ++nh) {
                int nrow = wn + nh * 16 + (lane & 7) + ((lane >> 4) << 3);
                int col  = k0 + (((lane >> 3) & 1) << 3);
                uint32_t addr = bBase + sw128((uint32_t)(nrow * 128 + col * 2));
                uint32_t r0, r1, r2, r3;
                asm volatile("ldmatrix.sync.aligned.m8n8.x4.shared.b16 {%0,%1,%2,%3}, [%4];"
                             : "=r"(r0), "=r"(r1), "=r"(r2), "=r"(r3)
                             : "r"(addr));
                bfr[nh * 2][0] = r0;     bfr[nh * 2][1] = r1;
                bfr[nh * 2 + 1][0] = r2; bfr[nh * 2 + 1][1] = r3;
            }

#pragma unroll
            for (int mt = 0; mt < 4; ++mt)
#pragma unroll
                for (int nt = 0; nt < 4; ++nt) {
                    asm volatile(
                        "mma.sync.aligned.m16n8k16.row.col.f32.f16.f16.f32 "
                        "{%0,%1,%2,%3}, {%4,%5,%6,%7}, {%8,%9}, {%0,%1,%2,%3};"
                        : "+f"(c[mt][nt][0]), "+f"(c[mt][nt][1]),
                          "+f"(c[mt][nt][2]), "+f"(c[mt][nt][3])
                        : "r"(a[mt][0]), "r"(a[mt][1]), "r"(a[mt][2]), "r"(a[mt][3]),
                          "r"(bfr[nt][0]), "r"(bfr[nt][1]));
                }
        }

        // ---- Epilogue: v = exp2(k2*gram - l2s*qi - l2s*qj), direct store ----
        const float* sSqI = sSq + buf * 256;
        const float* sSqJ = sSqI + 128;

        float sqj[4][2];
#pragma unroll
        for (int nt = 0; nt < 4; ++nt) {
            int cc = wn + nt * 8 + 2 * (lane & 3);
            sqj[nt][0] = -l2s * sSqJ[cc];
            sqj[nt][1] = -l2s * sSqJ[cc + 1];
        }

#pragma unroll
        for (int mt = 0; mt < 4; ++mt) {
            int rl = wm + mt * 16 + (lane >> 2);
            float qi0 = -l2s * sSqI[rl];
            float qi1 = -l2s * sSqI[rl + 8];
            int r = i0 + rl;
#pragma unroll
            for (int nt = 0; nt < 4; ++nt) {
                c[mt][nt][0] = exp2f(fmaf(k2, c[mt][nt][0], qi0) + sqj[nt][0]);
                c[mt][nt][1] = exp2f(fmaf(k2, c[mt][nt][1], qi0) + sqj[nt][1]);
                c[mt][nt][2] = exp2f(fmaf(k2, c[mt][nt][2], qi1) + sqj[nt][0]);
                c[mt][nt][3] = exp2f(fmaf(k2, c[mt][nt][3], qi1) + sqj[nt][1]);
                int cc = j0 + wn + nt * 8 + 2 * (lane & 3);
                float2 v0, v1;
                v0.x = c[mt][nt][0]; v0.y = c[mt][nt][1];
                v1.x = c[mt][nt][2]; v1.y = c[mt][nt][3];
                float* o = out + ((size_t)b * BN + r) * BN + cc;
                __stcs((float2*)o, v0);
                __stcs((float2*)(o + (size_t)8 * BN), v1);
            }
        }

        // ---- Mirror store via smem transpose (staging aliases CURRENT buffer) ----
        if (i0 != j0) {
            float* stg = (float*)(smem + (size_t)buf * 32768u);
#pragma unroll
            for (int h = 0; h < 2; ++h) {
                __syncthreads();   // all MMA reads of this buffer done / previous pass consumed
#pragma unroll
                for (int mt = 0; mt < 4; ++mt)
#pragma unroll
                    for (int nt2 = 0; nt2 < 2; ++nt2) {
                        int nt = 2 * h + nt2;
#pragma unroll
                        for (int q = 0; q < 4; ++q) {
                            int r  = wm + mt * 16 + (lane >> 2) + 8 * (q >> 1);
                            int cc = wn + nt * 8 + 2 * (lane & 3) + (q & 1);
                            int srow  = ((cc >> 5) << 4) | (cc & 15);
                            int chunk = (r >> 2) ^ (cc & 7);
                            stg[srow * 128 + chunk * 4 + (r & 3)] = c[mt][nt][q];
                        }
                    }
                __syncthreads();
#pragma unroll
                for (int itx = 0; itx < 8; ++itx) {
                    int idx   = tid + itx * 256;
                    int srow  = idx >> 5;
                    int chunk = idx & 31;
                    int cc = ((srow >> 4) << 5) + 16 * h + (srow & 15);
                    int rchunk = chunk ^ (srow & 7);
                    float4 v4 = *(float4*)&stg[srow * 128 + rchunk * 4];
                    __stcs((float4*)(out + ((size_t)b * BN + j0 + cc) * BN + i0 + chunk * 4), v4);
                }
            }
        }

        if (!have_next) break;
        asm volatile("cp.async.wait_group 0;");
        __syncthreads();
        task = ntask; b = nb; i0 = ni; j0 = nj;
        ++it;
    }
}

extern "C" void kernel_launch(void* const* d_in, const int* in_sizes, int n_in,
                              void* d_out, int out_size) {
    (void)in_sizes; (void)n_in; (void)out_size;
    const float* emb = (const float*)d_in[1];  // d_in[0] = adj_in (unused by reference)
    float* out = (float*)d_out;

    cudaFuncSetAttribute(gemm_kernel, cudaFuncAttributeMaxDynamicSharedMemorySize, 69632);

    dim3 gc(BN / 64, NB);
    convert_reduce_kernel<<<gc, 256>>>(emb);
    gemm_kernel<<<GRID_P, 256, 69632>>>(out);
}

// round 6
// speedup vs baseline: 1.8776x; 1.0198x over previous
#include <cuda_runtime.h>
#include <cuda_fp16.h>
#include <stdint.h>

#define NB 8
#define BF 64
#define BN 2048
#define GRID_P 296            // persistent CTAs (148 SMs x 2)
#define NPAIR 136             // upper-triangle 16x16 tile pairs
#define NTASK (NPAIR * NB)    // 1088

// smem layout (dynamic):
//   [0,32K)       buf0: A(16K)|B(16K)
//   [32K,64K)     buf1: A|B
//   [64K,96K)     per-warp transpose staging, 8 x 4KB
//   [96K,+2K)     sq[2][I|J][128]
//   [+2K,+4B)     scale
#define SMEM_STAGE 65536
#define SMEM_SQ    98304
#define SMEM_TOTAL (98304 + 2048 + 16)

// Scratch
__device__ __half g_emb_t[NB * BN * BF];   // transposed: [b][n][f], f contiguous (2 MB)
__device__ float  g_sqn[NB * BN];
__device__ float  g_part_sum[256];
__device__ float  g_part_sq[256];

// ---------------- Pass 1: convert f32->f16 transposed + sqn + std partial sums ----------------
__global__ void convert_reduce_kernel(const float* __restrict__ emb) {
    int b   = blockIdx.y;
    int tid = threadIdx.x;
    int fq  = tid & 3;
    int nl  = tid >> 2;
    int n   = blockIdx.x * 64 + nl;

    const float* e = emb + (size_t)b * BF * BN + (size_t)(fq * 16) * BN + n;

    float s = 0.f, s2 = 0.f, sq = 0.f;
    __half2 hv[8];
#pragma unroll
    for (int i = 0; i < 16; i += 2) {
        float v0 = e[(size_t)i * BN];
        float v1 = e[(size_t)(i + 1) * BN];
        s  += v0 + v1;
        s2 += v0 * v0 + v1 * v1;
        __half h0 = __float2half(v0), h1 = __float2half(v1);
        float w0 = __half2float(h0), w1 = __half2float(h1);
        sq += w0 * w0 + w1 * w1;
        hv[i >> 1] = __halves2half2(h0, h1);
    }
    sq += __shfl_xor_sync(0xffffffffu, sq, 1);
    sq += __shfl_xor_sync(0xffffffffu, sq, 2);
    if (fq == 0) g_sqn[b * BN + n] = sq;

    uint4* dst = (uint4*)(g_emb_t + ((size_t)b * BN + n) * BF + fq * 16);
    const uint4* src = (const uint4*)hv;
    dst[0] = src[0];
    dst[1] = src[1];

    __shared__ float sh[256], sh2[256];
    sh[tid] = s; sh2[tid] = s2;
    __syncthreads();
    for (int o = 128; o > 0; o >>= 1) {
        if (tid < o) { sh[tid] += sh[tid + o]; sh2[tid] += sh2[tid + o]; }
        __syncthreads();
    }
    if (tid == 0) {
        int bi = b * 32 + blockIdx.x;
        g_part_sum[bi] = sh[0];
        g_part_sq[bi]  = sh2[0];
    }
}

// XOR swizzle for 128B rows
__device__ __forceinline__ uint32_t sw128(uint32_t off) {
    return off ^ (((off >> 7) & 7u) << 4);
}

__device__ __forceinline__ void decode_task(int task, int& b, int& i0, int& j0) {
    b = task / NPAIR;
    int t = task - b * NPAIR;
    int ti = (int)(16.5f - sqrtf(272.25f - 2.0f * (float)t));
    if (ti > 0 && 16 * ti - (ti * (ti - 1)) / 2 > t) --ti;
    while (16 * (ti + 1) - ((ti + 1) * ti) / 2 <= t) ++ti;
    int tj = ti + (t - (16 * ti - (ti * (ti - 1)) / 2));
    i0 = ti * 128;
    j0 = tj * 128;
}

__device__ __forceinline__ void issue_load(int b, int i0, int j0,
                                           uint32_t abBase, uint32_t sqBase, int tid) {
    const char* EA = (const char*)(g_emb_t + ((size_t)b * BN + i0) * BF);
    const char* EB = (const char*)(g_emb_t + ((size_t)b * BN + j0) * BF);
#pragma unroll
    for (int tt = 0; tt < 4; ++tt) {
        uint32_t off = (uint32_t)(tid + tt * 256) * 16u;
        uint32_t sw  = sw128(off);
        asm volatile("cp.async.ca.shared.global [%0], [%1], 16;" :: "r"(abBase + sw),          "l"(EA + off));
        asm volatile("cp.async.ca.shared.global [%0], [%1], 16;" :: "r"(abBase + 16384u + sw), "l"(EB + off));
    }
    if (tid < 32) {
        const char* gI = (const char*)(g_sqn + b * BN + i0) + tid * 16;
        const char* gJ = (const char*)(g_sqn + b * BN + j0) + tid * 16;
        asm volatile("cp.async.ca.shared.global [%0], [%1], 16;" :: "r"(sqBase + tid * 16u),        "l"(gI));
        asm volatile("cp.async.ca.shared.global [%0], [%1], 16;" :: "r"(sqBase + 512u + tid * 16u), "l"(gJ));
    }
}

// ---------------- Pass 2: persistent upper-triangle Gram GEMM + exp + mirrored store ----------------
__global__ __launch_bounds__(256, 2) void gemm_kernel(float* __restrict__ out) {
    extern __shared__ __align__(16) char smem[];
    float* sSq     = (float*)(smem + SMEM_SQ);
    float* s_scale = (float*)(smem + SMEM_SQ + 2048);

    int tid = threadIdx.x;
    uint32_t smemBase = (uint32_t)__cvta_generic_to_shared(smem);
    uint32_t sqBaseU  = smemBase + SMEM_SQ;

    int task = blockIdx.x;
    int b, i0, j0;
    decode_task(task, b, i0, j0);
    issue_load(b, i0, j0, smemBase, sqBaseU, tid);
    asm volatile("cp.async.commit_group;");

    // scale reduction, once per CTA (overlapped with first load)
    if (tid < 32) {
        float ps = 0.f, pq = 0.f;
#pragma unroll
        for (int i = 0; i < 8; ++i) {
            ps += g_part_sum[tid + 32 * i];
            pq += g_part_sq[tid + 32 * i];
        }
#pragma unroll
        for (int o = 16; o > 0; o >>= 1) {
            ps += __shfl_xor_sync(0xffffffffu, ps, o);
            pq += __shfl_xor_sync(0xffffffffu, pq, o);
        }
        if (tid == 0) {
            double nn  = (double)(NB * BF * BN);
            double var = ((double)pq - (double)ps * (double)ps / nn) / (nn - 1.0);
            *s_scale = (float)(1.4426950408889634 / (var * (double)BF * 2.0));
        }
    }

    asm volatile("cp.async.wait_group 0;");
    __syncthreads();

    int warp = tid >> 5, lane = tid & 31;
    int wm = (warp >> 2) * 64;
    int wn = (warp & 3) * 32;
    float l2s = *s_scale;
    float k2  = 2.f * l2s;
    float* wstg = (float*)(smem + SMEM_STAGE + warp * 4096);

    int it = 0;
    while (true) {
        int buf = it & 1;
        uint32_t aBase = smemBase + (uint32_t)buf * 32768u;
        uint32_t bBase = aBase + 16384u;

        // prefetch next task into other buffer
        int ntask = task + GRID_P;
        bool have_next = ntask < NTASK;
        int nb, ni, nj;
        if (have_next) {
            decode_task(ntask, nb, ni, nj);
            issue_load(nb, ni, nj, smemBase + (uint32_t)(buf ^ 1) * 32768u,
                       sqBaseU + (uint32_t)(buf ^ 1) * 1024u, tid);
        }
        asm volatile("cp.async.commit_group;");

        // ---- MMA ----
        float c[4][4][4];
#pragma unroll
        for (int mt = 0; mt < 4; ++mt)
#pragma unroll
            for (int nt = 0; nt < 4; ++nt)
#pragma unroll
                for (int q = 0; q < 4; ++q) c[mt][nt][q] = 0.f;

#pragma unroll
        for (int kk = 0; kk < 4; ++kk) {
            int k0 = kk * 16;

            uint32_t a[4][4];
#pragma unroll
            for (int mt = 0; mt < 4; ++mt) {
                int row = wm + mt * 16 + (lane & 15);
                int col = k0 + ((lane >> 4) << 3);
                uint32_t addr = aBase + sw128((uint32_t)(row * 128 + col * 2));
                asm volatile("ldmatrix.sync.aligned.m8n8.x4.shared.b16 {%0,%1,%2,%3}, [%4];"
                             : "=r"(a[mt][0]), "=r"(a[mt][1]), "=r"(a[mt][2]), "=r"(a[mt][3])
                             : "r"(addr));
            }

            uint32_t bfr[4][2];
#pragma unroll
            for (int nh = 0; nh < 2; ++nh) {
                int nrow = wn + nh * 16 + (lane & 7) + ((lane >> 4) << 3);
                int col  = k0 + (((lane >> 3) & 1) << 3);
                uint32_t addr = bBase + sw128((uint32_t)(nrow * 128 + col * 2));
                uint32_t r0, r1, r2, r3;
                asm volatile("ldmatrix.sync.aligned.m8n8.x4.shared.b16 {%0,%1,%2,%3}, [%4];"
                             : "=r"(r0), "=r"(r1), "=r"(r2), "=r"(r3)
                             : "r"(addr));
                bfr[nh * 2][0] = r0;     bfr[nh * 2][1] = r1;
                bfr[nh * 2 + 1][0] = r2; bfr[nh * 2 + 1][1] = r3;
            }

#pragma unroll
            for (int mt = 0; mt < 4; ++mt)
#pragma unroll
                for (int nt = 0; nt < 4; ++nt) {
                    asm volatile(
                        "mma.sync.aligned.m16n8k16.row.col.f32.f16.f16.f32 "
                        "{%0,%1,%2,%3}, {%4,%5,%6,%7}, {%8,%9}, {%0,%1,%2,%3};"
                        : "+f"(c[mt][nt][0]), "+f"(c[mt][nt][1]),
                          "+f"(c[mt][nt][2]), "+f"(c[mt][nt][3])
                        : "r"(a[mt][0]), "r"(a[mt][1]), "r"(a[mt][2]), "r"(a[mt][3]),
                          "r"(bfr[nt][0]), "r"(bfr[nt][1]));
                }
        }

        // ---- Epilogue: v = exp2(k2*gram - l2s*qi - l2s*qj), direct store ----
        const float* sSqI = sSq + buf * 256;
        const float* sSqJ = sSqI + 128;

        float sqj[4][2];
#pragma unroll
        for (int nt = 0; nt < 4; ++nt) {
            int cc = wn + nt * 8 + 2 * (lane & 3);
            sqj[nt][0] = -l2s * sSqJ[cc];
            sqj[nt][1] = -l2s * sSqJ[cc + 1];
        }

#pragma unroll
        for (int mt = 0; mt < 4; ++mt) {
            int rl = wm + mt * 16 + (lane >> 2);
            float qi0 = -l2s * sSqI[rl];
            float qi1 = -l2s * sSqI[rl + 8];
            int r = i0 + rl;
#pragma unroll
            for (int nt = 0; nt < 4; ++nt) {
                c[mt][nt][0] = exp2f(fmaf(k2, c[mt][nt][0], qi0) + sqj[nt][0]);
                c[mt][nt][1] = exp2f(fmaf(k2, c[mt][nt][1], qi0) + sqj[nt][1]);
                c[mt][nt][2] = exp2f(fmaf(k2, c[mt][nt][2], qi1) + sqj[nt][0]);
                c[mt][nt][3] = exp2f(fmaf(k2, c[mt][nt][3], qi1) + sqj[nt][1]);
                int cc = j0 + wn + nt * 8 + 2 * (lane & 3);
                float2 v0, v1;
                v0.x = c[mt][nt][0]; v0.y = c[mt][nt][1];
                v1.x = c[mt][nt][2]; v1.y = c[mt][nt][3];
                float* o = out + ((size_t)b * BN + r) * BN + cc;
                __stcs((float2*)o, v0);
                __stcs((float2*)(o + (size_t)8 * BN), v1);
            }
        }

        // ---- Mirror store: per-warp private transpose, NO block barriers ----
        if (i0 != j0) {
#pragma unroll
            for (int h = 0; h < 2; ++h) {
                // stage 32x32 chunk (rows wm+32h..+32, cols wn..wn+32) into warp slab
#pragma unroll
                for (int mt2 = 0; mt2 < 2; ++mt2) {
                    int mt = 2 * h + mt2;
#pragma unroll
                    for (int nt = 0; nt < 4; ++nt)
#pragma unroll
                        for (int q = 0; q < 4; ++q) {
                            int rloc = mt2 * 16 + (lane >> 2) + 8 * (q >> 1);   // 0..31
                            int cc   = nt * 8 + 2 * (lane & 3) + (q & 1);        // 0..31
                            int word = cc * 32 + ((((rloc >> 2) ^ (cc & 7)) << 2) | (rloc & 3));
                            wstg[word] = c[mt][nt][q];
                        }
                }
                __syncwarp();
#pragma unroll
                for (int itx = 0; itx < 8; ++itx) {
                    int cc = itx * 4 + (lane >> 3);     // col within warp frag
                    int f  = lane & 7;
                    int fs = f ^ (cc & 7);
                    float4 v = *(float4*)&wstg[cc * 32 + 4 * fs];
                    __stcs((float4*)(out + ((size_t)b * BN + j0 + wn + cc) * BN
                                         + i0 + wm + 32 * h + 4 * f), v);
                }
                __syncwarp();
            }
        }

        if (!have_next) break;
        asm volatile("cp.async.wait_group 0;");
        __syncthreads();
        task = ntask; b = nb; i0 = ni; j0 = nj;
        ++it;
    }
}

extern "C" void kernel_launch(void* const* d_in, const int* in_sizes, int n_in,
                              void* d_out, int out_size) {
    (void)in_sizes; (void)n_in; (void)out_size;
    const float* emb = (const float*)d_in[1];  // d_in[0] = adj_in (unused by reference)
    float* out = (float*)d_out;

    cudaFuncSetAttribute(gemm_kernel, cudaFuncAttributeMaxDynamicSharedMemorySize, SMEM_TOTAL);

    dim3 gc(BN / 64, NB);
    convert_reduce_kernel<<<gc, 256>>>(emb);
    gemm_kernel<<<GRID_P, 256, SMEM_TOTAL>>>(out);
}